// round 5
// baseline (speedup 1.0000x reference)
#include <cuda_runtime.h>
#include <cuda_bf16.h>
#include <math.h>
#include <stdint.h>

#define NNODES 100000
#define NEDGES 3200000
#define NF 256
#define KX 768   // extended K = 3 * 256 (kc-major: per 64-chunk [Bhi|Blo|Bhi])

// ---------------- scratch (device globals; no allocs allowed) ----------------
__device__ float g_bufA[(size_t)NNODES * NF];
__device__ float g_bufB[(size_t)NNODES * NF];
__device__ __nv_bfloat16 g_Abf[(size_t)NNODES * 512];   // A split: [hi(256) | lo(256)]
__device__ int   g_rowptr[NNODES + 1];
__device__ int   g_cursor[NNODES];
__device__ int   g_cols[NEDGES];
__device__ float g_wts[NEDGES];
__device__ __nv_bfloat16 g_Wp[3][NF * KX];

// ---------------- helpers ----------------
__device__ __forceinline__ uint32_t smem_u32(const void* p) {
    uint32_t a;
    asm("{ .reg .u64 t; cvta.to.shared.u64 t, %1; cvt.u32.u64 %0, t; }" : "=r"(a) : "l"(p));
    return a;
}

#define LDSM_X4(r0, r1, r2, r3, addr) \
    asm volatile("ldmatrix.sync.aligned.m8n8.x4.shared.b16 {%0,%1,%2,%3}, [%4];" \
                 : "=r"(r0), "=r"(r1), "=r"(r2), "=r"(r3) : "r"(addr))

__device__ __forceinline__ void mma_bf16(float* d, const uint32_t* a, const uint32_t* b) {
    asm volatile(
        "mma.sync.aligned.m16n8k16.row.col.f32.bf16.bf16.f32 "
        "{%0,%1,%2,%3}, {%4,%5,%6,%7}, {%8,%9}, {%0,%1,%2,%3};"
        : "+f"(d[0]), "+f"(d[1]), "+f"(d[2]), "+f"(d[3])
        : "r"(a[0]), "r"(a[1]), "r"(a[2]), "r"(a[3]), "r"(b[0]), "r"(b[1]));
}

#define CP_ASYNC16(dst, src) \
    asm volatile("cp.async.cg.shared.global [%0], [%1], 16;" :: "r"(dst), "l"(src))
#define CP_COMMIT() asm volatile("cp.async.commit_group;")
#define CP_WAIT1() asm volatile("cp.async.wait_group 1;")
#define CP_WAIT0() asm volatile("cp.async.wait_group 0;")

// ---------------- weight prep: W[K][N] fp32 -> B'[N][KX] bf16, kc-major ----------------
__global__ void prep_w_bf16(const float* __restrict__ W, __nv_bfloat16* __restrict__ Bp) {
    int n = blockIdx.x;
    int k = threadIdx.x;
    float v = W[(size_t)k * NF + n];
    __nv_bfloat16 h = __float2bfloat16(v);
    __nv_bfloat16 l = __float2bfloat16(v - __bfloat162float(h));
    int kc = k >> 6, kr = k & 63;
    __nv_bfloat16* dst = Bp + (size_t)n * KX + kc * 192 + kr;
    dst[0] = h;      // p0: Ahi*Bhi
    dst[64] = l;     // p1: Ahi*Blo
    dst[128] = h;    // p2: Alo*Bhi
}

// ---------------- split fp32 [M,256] -> bf16 [M,512] (hi|lo) ----------------
__global__ void split_A_kernel(const float* __restrict__ src,
                               __nv_bfloat16* __restrict__ dst, int M) {
    int i = blockIdx.x * blockDim.x + threadIdx.x;
    if (i >= M * 64) return;
    int row = i >> 6, q = i & 63;
    float4 v = ((const float4*)src)[i];
    __nv_bfloat16 h[4], l[4];
    const float* f = (const float*)&v;
#pragma unroll
    for (int e = 0; e < 4; e++) {
        h[e] = __float2bfloat16(f[e]);
        l[e] = __float2bfloat16(f[e] - __bfloat162float(h[e]));
    }
    *(uint2*)(dst + (size_t)row * 512 + q * 4) = *(uint2*)h;
    *(uint2*)(dst + (size_t)row * 512 + 256 + q * 4) = *(uint2*)l;
}

// ---------------- bf16x3 GEMM, 3-stage cp.async pipeline ----------------
// A: bf16 [M,512] hi|lo; B': bf16 [256,768] kc-major. BM=128, BN=256, BK=64.
// OUT_SPLIT: write bf16 split [M,512] (for next GEMM). Else fp32 [M,256].
#define PITCH 72
#define A_SZ (128 * PITCH * 2)
#define B_SZ (256 * PITCH * 2)
#define STAGE_SZ (A_SZ + B_SZ)
#define GEMM_SMEM (3 * STAGE_SZ)

template <bool OUT_SPLIT>
__global__ void __launch_bounds__(512) gemm_bf16x3_kernel(
    const __nv_bfloat16* __restrict__ Ab, const __nv_bfloat16* __restrict__ Bp,
    const float* __restrict__ bias, float* __restrict__ C,
    __nv_bfloat16* __restrict__ Cb, int M) {
    extern __shared__ char smem[];
    uint32_t sbase = smem_u32(smem);

    int tid = threadIdx.x, lane = tid & 31, wid = tid >> 5;
    int m0 = blockIdx.x * 128;
    int wm = (wid >> 2) * 32;
    int wn = (wid & 3) * 64;

    // loaders
    int arow = tid >> 2, aq = tid & 3;                  // A: 4 thr/row, 2x16B each
    int gmA = m0 + arow; if (gmA >= M) gmA = M - 1;
    int brow = tid >> 1, bh = tid & 1;                  // B: 2 thr/row, 4x16B each

    float acc[2][8][4];
#pragma unroll
    for (int i = 0; i < 2; i++)
#pragma unroll
        for (int j = 0; j < 8; j++)
#pragma unroll
            for (int q = 0; q < 4; q++) acc[i][j][q] = 0.f;

    auto issue = [&](int it, int stg) {
        int kc = it / 3, p = it - kc * 3;
        uint32_t sA = sbase + stg * STAGE_SZ;
        uint32_t sB = sA + A_SZ;
        const __nv_bfloat16* asrc =
            Ab + (size_t)gmA * 512 + (p == 2 ? 256 : 0) + kc * 64 + aq * 16;
        uint32_t adst = sA + (uint32_t)(arow * PITCH + aq * 16) * 2;
        CP_ASYNC16(adst, asrc);
        CP_ASYNC16(adst + 16, asrc + 8);
        const __nv_bfloat16* bsrc = Bp + (size_t)brow * KX + it * 64 + bh * 32;
        uint32_t bdst = sB + (uint32_t)(brow * PITCH + bh * 32) * 2;
#pragma unroll
        for (int j = 0; j < 4; j++) CP_ASYNC16(bdst + j * 16, bsrc + j * 8);
        CP_COMMIT();
    };

    auto compute = [&](int stg) {
        uint32_t sA = sbase + stg * STAGE_SZ;
        uint32_t sB = sA + A_SZ;
#pragma unroll
        for (int ks = 0; ks < 4; ks++) {
            uint32_t af[2][4];
#pragma unroll
            for (int mt = 0; mt < 2; mt++) {
                uint32_t addr = sA +
                    (uint32_t)((wm + mt * 16 + (lane & 15)) * PITCH + ks * 16 +
                               ((lane >> 4) << 3)) * 2;
                LDSM_X4(af[mt][0], af[mt][1], af[mt][2], af[mt][3], addr);
            }
            uint32_t bf[4][4];
#pragma unroll
            for (int p = 0; p < 4; p++) {
                uint32_t addr = sB +
                    (uint32_t)((wn + p * 16 + ((lane >> 4) << 3) + (lane & 7)) * PITCH +
                               ks * 16 + ((lane >> 3) & 1) * 8) * 2;
                LDSM_X4(bf[p][0], bf[p][1], bf[p][2], bf[p][3], addr);
            }
#pragma unroll
            for (int mt = 0; mt < 2; mt++)
#pragma unroll
                for (int nt = 0; nt < 8; nt++)
                    mma_bf16(acc[mt][nt], af[mt], &bf[nt >> 1][(nt & 1) * 2]);
        }
    };

    issue(0, 0);
    issue(1, 1);
    for (int it = 0; it < 12; it++) {
        if (it < 11) CP_WAIT1(); else CP_WAIT0();
        __syncthreads();
        compute(it % 3);
        if (it + 2 < 12) issue(it + 2, (it + 2) % 3);
    }

    // epilogue
#pragma unroll
    for (int mt = 0; mt < 2; mt++) {
        int rr[2];
        rr[0] = m0 + wm + mt * 16 + (lane >> 2);
        rr[1] = rr[0] + 8;
#pragma unroll
        for (int nt = 0; nt < 8; nt++) {
            int n = wn + nt * 8 + (lane & 3) * 2;
            float b0 = __ldg(bias + n), b1 = __ldg(bias + n + 1);
#pragma unroll
            for (int h = 0; h < 2; h++) {
                int r = rr[h];
                if (r >= M) continue;
                float v0 = fmaxf(acc[mt][nt][h * 2 + 0] + b0, 0.f);
                float v1 = fmaxf(acc[mt][nt][h * 2 + 1] + b1, 0.f);
                if (OUT_SPLIT) {
                    __nv_bfloat16 h0 = __float2bfloat16(v0);
                    __nv_bfloat16 h1 = __float2bfloat16(v1);
                    __nv_bfloat16 l0 = __float2bfloat16(v0 - __bfloat162float(h0));
                    __nv_bfloat16 l1 = __float2bfloat16(v1 - __bfloat162float(h1));
                    __nv_bfloat162 ph; ph.x = h0; ph.y = h1;
                    __nv_bfloat162 pl; pl.x = l0; pl.y = l1;
                    *(__nv_bfloat162*)(Cb + (size_t)r * 512 + n) = ph;
                    *(__nv_bfloat162*)(Cb + (size_t)r * 512 + 256 + n) = pl;
                } else {
                    float2 o; o.x = v0; o.y = v1;
                    *(float2*)(C + (size_t)r * NF + n) = o;
                }
            }
        }
    }
}

// ---------------- CSR build ----------------
__global__ void hist_kernel(const int* __restrict__ erow, int E) {
    int i = blockIdx.x * blockDim.x + threadIdx.x;
    if (i < E) atomicAdd(&g_rowptr[erow[i]], 1);
}

__global__ void scan_kernel(int n) {
    __shared__ int part[1024];
    int t = threadIdx.x;
    int CH = (n + 1023) / 1024;
    int beg = t * CH;
    int end = min(beg + CH, n);
    int s = 0;
    for (int i = beg; i < end; i++) s += g_rowptr[i];
    part[t] = s;
    __syncthreads();
    for (int off = 1; off < 1024; off <<= 1) {
        int v = (t >= off) ? part[t - off] : 0;
        __syncthreads();
        part[t] += v;
        __syncthreads();
    }
    int base = (t == 0) ? 0 : part[t - 1];
    int run = base;
    for (int i = beg; i < end; i++) {
        int c = g_rowptr[i];
        g_rowptr[i] = run;
        g_cursor[i] = run;
        run += c;
    }
    if (t == 1023) g_rowptr[n] = part[1023];
}

__global__ void scatter_kernel(const int* __restrict__ erow,
                               const int* __restrict__ ecol,
                               const float* __restrict__ ew, int E) {
    int i = blockIdx.x * blockDim.x + threadIdx.x;
    if (i < E) {
        int r = erow[i];
        int pos = atomicAdd(&g_cursor[r], 1);
        g_cols[pos] = ecol[i];
        g_wts[pos] = ew[i];
    }
}

// ---------------- SPMM + residual: 2 warps/row, unroll x4, streaming stores ----------------
__global__ void spmm_res_kernel(const float* __restrict__ src,
                                float* __restrict__ dst, int n) {
    int gw = (blockIdx.x * blockDim.x + threadIdx.x) >> 5;
    int row = gw >> 1;
    if (row >= n) return;
    int half = gw & 1;
    int lane = threadIdx.x & 31;
    int fo = half * 32 + lane;
    const float4* s4 = (const float4*)src;
    float4 a = s4[(size_t)row * 64 + fo];
    int beg = g_rowptr[row], end = g_rowptr[row + 1];
    int e = beg;
    for (; e + 4 <= end; e += 4) {
        int c0 = __ldg(&g_cols[e]),     c1 = __ldg(&g_cols[e + 1]);
        int c2 = __ldg(&g_cols[e + 2]), c3 = __ldg(&g_cols[e + 3]);
        float w0 = __ldg(&g_wts[e]),     w1 = __ldg(&g_wts[e + 1]);
        float w2 = __ldg(&g_wts[e + 2]), w3 = __ldg(&g_wts[e + 3]);
        float4 v0 = s4[(size_t)c0 * 64 + fo];
        float4 v1 = s4[(size_t)c1 * 64 + fo];
        float4 v2 = s4[(size_t)c2 * 64 + fo];
        float4 v3 = s4[(size_t)c3 * 64 + fo];
        a.x += w0 * v0.x + w1 * v1.x + w2 * v2.x + w3 * v3.x;
        a.y += w0 * v0.y + w1 * v1.y + w2 * v2.y + w3 * v3.y;
        a.z += w0 * v0.z + w1 * v1.z + w2 * v2.z + w3 * v3.z;
        a.w += w0 * v0.w + w1 * v1.w + w2 * v2.w + w3 * v3.w;
    }
    for (; e < end; e++) {
        int c = __ldg(&g_cols[e]);
        float w = __ldg(&g_wts[e]);
        float4 v = s4[(size_t)c * 64 + fo];
        a.x += w * v.x; a.y += w * v.y; a.z += w * v.z; a.w += w * v.w;
    }
    __stcs(((float4*)dst) + (size_t)row * 64 + fo, a);
}

// ---------------- fused final GEMM (N=40) + log_softmax ----------------
__global__ void __launch_bounds__(256) gemm40_lsm_kernel(
    const float* __restrict__ A, const float* __restrict__ B,
    const float* __restrict__ bias, float* __restrict__ out, int M) {
    __shared__ float As[16][132];
    __shared__ float Bs[16][64];
    __shared__ float ls[128][44];
    int tid = threadIdx.x;
    int tn = tid % 16, tm = tid / 16;
    int m0 = blockIdx.x * 128;
    float acc[8][4];
#pragma unroll
    for (int i = 0; i < 8; i++)
#pragma unroll
        for (int j = 0; j < 4; j++) acc[i][j] = 0.f;

    for (int k0 = 0; k0 < NF; k0 += 16) {
        for (int i = tid; i < 128 * 16; i += 256) {
            int r = i >> 4, c = i & 15;
            int gm = m0 + r;
            As[c][r] = (gm < M) ? A[(size_t)gm * NF + k0 + c] : 0.f;
        }
        for (int i = tid; i < 16 * 64; i += 256) {
            int r = i >> 6, c = i & 63;
            Bs[r][c] = (c < 40) ? B[(size_t)(k0 + r) * 40 + c] : 0.f;
        }
        __syncthreads();
#pragma unroll
        for (int k = 0; k < 16; k++) {
            float av[8], bv[4];
#pragma unroll
            for (int i = 0; i < 8; i++) av[i] = As[k][tm * 8 + i];
#pragma unroll
            for (int j = 0; j < 4; j++) bv[j] = Bs[k][tn * 4 + j];
#pragma unroll
            for (int i = 0; i < 8; i++)
#pragma unroll
                for (int j = 0; j < 4; j++) acc[i][j] += av[i] * bv[j];
        }
        __syncthreads();
    }
#pragma unroll
    for (int i = 0; i < 8; i++)
#pragma unroll
        for (int j = 0; j < 4; j++) {
            int c = tn * 4 + j;
            if (c < 40) ls[tm * 8 + i][c] = acc[i][j] + bias[c];
        }
    __syncthreads();
    int wid = tid >> 5, lane = tid & 31;
    for (int i = 0; i < 16; i++) {
        int r = wid * 16 + i;
        int gr = m0 + r;
        if (gr >= M) continue;
        float v0 = ls[r][lane];
        float v1 = (lane < 8) ? ls[r][32 + lane] : -INFINITY;
        float m = fmaxf(v0, v1);
#pragma unroll
        for (int off = 16; off; off >>= 1) m = fmaxf(m, __shfl_xor_sync(0xffffffffu, m, off));
        float s = __expf(v0 - m) + ((lane < 8) ? __expf(v1 - m) : 0.f);
#pragma unroll
        for (int off = 16; off; off >>= 1) s += __shfl_xor_sync(0xffffffffu, s, off);
        float lse = m + __logf(s);
        out[(size_t)gr * 40 + lane] = v0 - lse;
        if (lane < 8) out[(size_t)gr * 40 + 32 + lane] = v1 - lse;
    }
}

// ---------------- launch ----------------
extern "C" void kernel_launch(void* const* d_in, const int* in_sizes, int n_in,
                              void* d_out, int out_size) {
    const float* x    = (const float*)d_in[0];
    const int*   erow = (const int*)d_in[1];
    const int*   ecol = (const int*)d_in[2];
    const float* ew   = (const float*)d_in[3];
    const float* W1 = (const float*)d_in[4];
    const float* b1 = (const float*)d_in[5];
    const float* W2 = (const float*)d_in[6];
    const float* b2 = (const float*)d_in[7];
    const float* W3 = (const float*)d_in[8];
    const float* b3 = (const float*)d_in[9];
    const float* W4 = (const float*)d_in[10];
    const float* b4 = (const float*)d_in[11];
    float* out = (float*)d_out;

    int E = in_sizes[1];
    int n = in_sizes[0] / NF;

    float *bufA, *bufB;
    __nv_bfloat16 *wp, *abf;
    int* rowptr;
    cudaGetSymbolAddress((void**)&bufA, g_bufA);
    cudaGetSymbolAddress((void**)&bufB, g_bufB);
    cudaGetSymbolAddress((void**)&rowptr, g_rowptr);
    cudaGetSymbolAddress((void**)&wp, g_Wp);
    cudaGetSymbolAddress((void**)&abf, g_Abf);

    cudaFuncSetAttribute(gemm_bf16x3_kernel<true>,
                         cudaFuncAttributeMaxDynamicSharedMemorySize, GEMM_SMEM);
    cudaFuncSetAttribute(gemm_bf16x3_kernel<false>,
                         cudaFuncAttributeMaxDynamicSharedMemorySize, GEMM_SMEM);

    // CSR build
    cudaMemsetAsync(rowptr, 0, (size_t)(n + 1) * sizeof(int));
    hist_kernel<<<(E + 255) / 256, 256>>>(erow, E);
    scan_kernel<<<1, 1024>>>(n);
    scatter_kernel<<<(E + 255) / 256, 256>>>(erow, ecol, ew, E);

    int spmm_blocks = (n * 64 + 255) / 256;
    int gemm_grid = (n + 127) / 128;
    int split_blocks = (n * 64 + 255) / 256;

    // h0 = x + spmm(x)                      -> bufA   [4th kernel: profiled]
    spmm_res_kernel<<<spmm_blocks, 256>>>(x, bufA, n);

    // weight prep
    prep_w_bf16<<<256, 256>>>(W1, wp + 0 * (size_t)NF * KX);
    prep_w_bf16<<<256, 256>>>(W2, wp + 1 * (size_t)NF * KX);
    prep_w_bf16<<<256, 256>>>(W3, wp + 2 * (size_t)NF * KX);

    // split h0 -> Abf
    split_A_kernel<<<split_blocks, 256>>>(bufA, abf, n);
    // h1 = relu(h0 @ W1 + b1)  (bf16-split out -> Abf, overwritten in place is NOT ok;
    //  write into Abf directly: gemm reads Abf while writing Abf rows it already consumed?
    //  unsafe; use ping-pong: read Abf, write split into bufB's bytes? bufB is fp32 [M,256]
    //  = 102.4MB, same size as a bf16 [M,512]. Reuse bufB as the split output.)
    gemm_bf16x3_kernel<true><<<gemm_grid, 512, GEMM_SMEM>>>(
        abf, wp + 0 * (size_t)NF * KX, b1, nullptr, (__nv_bfloat16*)bufB, n);
    // h2 = relu(h1 @ W2 + b2)               -> bufA (fp32, feeds spmm)
    gemm_bf16x3_kernel<false><<<gemm_grid, 512, GEMM_SMEM>>>(
        (const __nv_bfloat16*)bufB, wp + 1 * (size_t)NF * KX, b2, bufA, nullptr, n);
    // h3 = h2 + spmm(h2)                    -> bufB(fp32 view)  ... need distinct buffer:
    //  bufB currently holds h1-split (dead after GEMM2). Reuse bufB as fp32 dst.
    spmm_res_kernel<<<spmm_blocks, 256>>>(bufA, bufB, n);
    // split h3 -> Abf
    split_A_kernel<<<split_blocks, 256>>>(bufB, abf, n);
    // h4 = relu(h3 @ W3 + b3)               -> bufA (fp32, feeds final)
    gemm_bf16x3_kernel<false><<<gemm_grid, 512, GEMM_SMEM>>>(
        abf, wp + 2 * (size_t)NF * KX, b3, bufA, nullptr, n);
    // logits + log_softmax                  -> d_out
    gemm40_lsm_kernel<<<gemm_grid, 256>>>(bufA, W4, b4, out, n);
}

// round 6
// speedup vs baseline: 1.1583x; 1.1583x over previous
#include <cuda_runtime.h>
#include <cuda_fp16.h>
#include <math.h>
#include <stdint.h>

#define NNODES 100000
#define NEDGES 3200000
#define NF 256

// ---------------- scratch (device globals; no allocs allowed) ----------------
__device__ float g_bufA[(size_t)NNODES * NF];           // fp32 [M,256]
__device__ float g_bufB[(size_t)NNODES * NF];           // fp32 [M,256] OR fp16-split [M,512]
__device__ __half g_Asp[(size_t)NNODES * 512];          // fp16 split [hi(256)|lo(256)]
__device__ int   g_rowptr[NNODES + 1];
__device__ int   g_cursor[NNODES];
__device__ int   g_cols[NEDGES];
__device__ float g_wts[NEDGES];
__device__ __half g_Wh[3][NF * NF];                     // fp16 weights, [N][K] K-major

// ---------------- helpers ----------------
__device__ __forceinline__ uint32_t smem_u32(const void* p) {
    uint32_t a;
    asm("{ .reg .u64 t; cvta.to.shared.u64 t, %1; cvt.u32.u64 %0, t; }" : "=r"(a) : "l"(p));
    return a;
}

#define LDSM_X4(r0, r1, r2, r3, addr) \
    asm volatile("ldmatrix.sync.aligned.m8n8.x4.shared.b16 {%0,%1,%2,%3}, [%4];" \
                 : "=r"(r0), "=r"(r1), "=r"(r2), "=r"(r3) : "r"(addr))

__device__ __forceinline__ void mma_f16(float* d, const uint32_t* a, const uint32_t* b) {
    asm volatile(
        "mma.sync.aligned.m16n8k16.row.col.f32.f16.f16.f32 "
        "{%0,%1,%2,%3}, {%4,%5,%6,%7}, {%8,%9}, {%0,%1,%2,%3};"
        : "+f"(d[0]), "+f"(d[1]), "+f"(d[2]), "+f"(d[3])
        : "r"(a[0]), "r"(a[1]), "r"(a[2]), "r"(a[3]), "r"(b[0]), "r"(b[1]));
}

#define CP_ASYNC16(dst, src) \
    asm volatile("cp.async.cg.shared.global [%0], [%1], 16;" :: "r"(dst), "l"(src))
#define CP_COMMIT() asm volatile("cp.async.commit_group;")
#define CP_WAIT1() asm volatile("cp.async.wait_group 1;")
#define CP_WAIT0() asm volatile("cp.async.wait_group 0;")

// pack 4 floats -> 4 fp16 hi + 4 fp16 lo (8B each)
__device__ __forceinline__ void split4(const float* f, uint2& hi, uint2& lo) {
    __half h[4], l[4];
#pragma unroll
    for (int e = 0; e < 4; e++) {
        h[e] = __float2half_rn(f[e]);
        l[e] = __float2half_rn(f[e] - __half2float(h[e]));
    }
    hi = *(uint2*)h;
    lo = *(uint2*)l;
}

// ---------------- weight prep: W[K][N] fp32 -> Wh[N][K] fp16 ----------------
__global__ void prep_w_f16(const float* __restrict__ W, __half* __restrict__ Bh) {
    int n = blockIdx.x;
    int k = threadIdx.x;
    Bh[(size_t)n * NF + k] = __float2half_rn(W[(size_t)k * NF + n]);
}

// ---------------- fp16x2 GEMM, 3-stage cp.async pipeline ----------------
// A: fp16 [M,512] (hi|lo); B: fp16 [256,256] K-major. C = relu(A@B^T + bias).
// K' = 512 -> 8 iterations of BK=64. iter it: kc=it>>1, p=it&1 (p=0:hi, p=1:lo).
#define PITCH 72
#define A_SZ (128 * PITCH * 2)
#define B_SZ (256 * PITCH * 2)
#define STAGE_SZ (A_SZ + B_SZ)
#define GEMM_SMEM (3 * STAGE_SZ)

template <bool OUT_SPLIT>
__global__ void __launch_bounds__(512) gemm_f16x2_kernel(
    const __half* __restrict__ Ah, const __half* __restrict__ Bh,
    const float* __restrict__ bias, float* __restrict__ C,
    __half* __restrict__ Cs, int M) {
    extern __shared__ char smem[];
    uint32_t sbase = smem_u32(smem);

    int tid = threadIdx.x, lane = tid & 31, wid = tid >> 5;
    int m0 = blockIdx.x * 128;
    int wm = (wid >> 2) * 32;
    int wn = (wid & 3) * 64;

    int arow = tid >> 2, aq = tid & 3;
    int gmA = m0 + arow; if (gmA >= M) gmA = M - 1;
    int brow = tid >> 1, bh = tid & 1;

    float acc[2][8][4];
#pragma unroll
    for (int i = 0; i < 2; i++)
#pragma unroll
        for (int j = 0; j < 8; j++)
#pragma unroll
            for (int q = 0; q < 4; q++) acc[i][j][q] = 0.f;

    auto issue = [&](int it, int stg) {
        int kc = it >> 1, p = it & 1;
        uint32_t sA = sbase + stg * STAGE_SZ;
        uint32_t sB = sA + A_SZ;
        const __half* asrc = Ah + (size_t)gmA * 512 + p * 256 + kc * 64 + aq * 16;
        uint32_t adst = sA + (uint32_t)(arow * PITCH + aq * 16) * 2;
        CP_ASYNC16(adst, asrc);
        CP_ASYNC16(adst + 16, asrc + 8);
        const __half* bsrc = Bh + (size_t)brow * NF + kc * 64 + bh * 32;
        uint32_t bdst = sB + (uint32_t)(brow * PITCH + bh * 32) * 2;
#pragma unroll
        for (int j = 0; j < 4; j++) CP_ASYNC16(bdst + j * 16, bsrc + j * 8);
        CP_COMMIT();
    };

    auto compute = [&](int stg) {
        uint32_t sA = sbase + stg * STAGE_SZ;
        uint32_t sB = sA + A_SZ;
#pragma unroll
        for (int ks = 0; ks < 4; ks++) {
            uint32_t af[2][4];
#pragma unroll
            for (int mt = 0; mt < 2; mt++) {
                uint32_t addr = sA +
                    (uint32_t)((wm + mt * 16 + (lane & 15)) * PITCH + ks * 16 +
                               ((lane >> 4) << 3)) * 2;
                LDSM_X4(af[mt][0], af[mt][1], af[mt][2], af[mt][3], addr);
            }
            uint32_t bf[4][4];
#pragma unroll
            for (int p = 0; p < 4; p++) {
                uint32_t addr = sB +
                    (uint32_t)((wn + p * 16 + ((lane >> 4) << 3) + (lane & 7)) * PITCH +
                               ks * 16 + ((lane >> 3) & 1) * 8) * 2;
                LDSM_X4(bf[p][0], bf[p][1], bf[p][2], bf[p][3], addr);
            }
#pragma unroll
            for (int mt = 0; mt < 2; mt++)
#pragma unroll
                for (int nt = 0; nt < 8; nt++)
                    mma_f16(acc[mt][nt], af[mt], &bf[nt >> 1][(nt & 1) * 2]);
        }
    };

    issue(0, 0);
    issue(1, 1);
    for (int it = 0; it < 8; it++) {
        if (it < 7) CP_WAIT1(); else CP_WAIT0();
        __syncthreads();
        compute(it % 3);
        if (it + 2 < 8) issue(it + 2, (it + 2) % 3);
    }

    // epilogue: bias + relu
#pragma unroll
    for (int mt = 0; mt < 2; mt++) {
        int rr[2];
        rr[0] = m0 + wm + mt * 16 + (lane >> 2);
        rr[1] = rr[0] + 8;
#pragma unroll
        for (int nt = 0; nt < 8; nt++) {
            int n = wn + nt * 8 + (lane & 3) * 2;
            float b0 = __ldg(bias + n), b1 = __ldg(bias + n + 1);
#pragma unroll
            for (int h = 0; h < 2; h++) {
                int r = rr[h];
                if (r >= M) continue;
                float v0 = fmaxf(acc[mt][nt][h * 2 + 0] + b0, 0.f);
                float v1 = fmaxf(acc[mt][nt][h * 2 + 1] + b1, 0.f);
                if (OUT_SPLIT) {
                    __half h0 = __float2half_rn(v0), h1 = __float2half_rn(v1);
                    __half l0 = __float2half_rn(v0 - __half2float(h0));
                    __half l1 = __float2half_rn(v1 - __half2float(h1));
                    __half ph[2] = {h0, h1}, pl[2] = {l0, l1};
                    *(uint32_t*)(Cs + (size_t)r * 512 + n) = *(uint32_t*)ph;
                    *(uint32_t*)(Cs + (size_t)r * 512 + 256 + n) = *(uint32_t*)pl;
                } else {
                    float2 o; o.x = v0; o.y = v1;
                    *(float2*)(C + (size_t)r * NF + n) = o;
                }
            }
        }
    }
}

// ---------------- CSR build ----------------
__global__ void hist_kernel(const int* __restrict__ erow, int E) {
    int i = blockIdx.x * blockDim.x + threadIdx.x;
    if (i < E) atomicAdd(&g_rowptr[erow[i]], 1);
}

__global__ void scan_kernel(int n) {
    __shared__ int part[1024];
    int t = threadIdx.x;
    int CH = (n + 1023) / 1024;
    int beg = t * CH;
    int end = min(beg + CH, n);
    int s = 0;
    for (int i = beg; i < end; i++) s += g_rowptr[i];
    part[t] = s;
    __syncthreads();
    for (int off = 1; off < 1024; off <<= 1) {
        int v = (t >= off) ? part[t - off] : 0;
        __syncthreads();
        part[t] += v;
        __syncthreads();
    }
    int base = (t == 0) ? 0 : part[t - 1];
    int run = base;
    for (int i = beg; i < end; i++) {
        int c = g_rowptr[i];
        g_rowptr[i] = run;
        g_cursor[i] = run;
        run += c;
    }
    if (t == 1023) g_rowptr[n] = part[1023];
}

__global__ void scatter_kernel(const int* __restrict__ erow,
                               const int* __restrict__ ecol,
                               const float* __restrict__ ew, int E) {
    int i = blockIdx.x * blockDim.x + threadIdx.x;
    if (i < E) {
        int r = erow[i];
        int pos = atomicAdd(&g_cursor[r], 1);
        g_cols[pos] = ecol[i];
        g_wts[pos] = ew[i];
    }
}

// ---------------- SPMM + residual -> fp16 split output ----------------
// dst[row] = split_fp16( src[row] + sum_e w * src[col] )
__global__ void spmm_res_split_kernel(const float* __restrict__ src,
                                      __half* __restrict__ dst, int n) {
    int gw = (blockIdx.x * blockDim.x + threadIdx.x) >> 5;
    int row = gw >> 1;
    if (row >= n) return;
    int half = gw & 1;
    int lane = threadIdx.x & 31;
    int fo = half * 32 + lane;
    const float4* s4 = (const float4*)src;
    float4 a = s4[(size_t)row * 64 + fo];
    int beg = g_rowptr[row], end = g_rowptr[row + 1];
    int e = beg;
    for (; e + 4 <= end; e += 4) {
        int c0 = __ldg(&g_cols[e]),     c1 = __ldg(&g_cols[e + 1]);
        int c2 = __ldg(&g_cols[e + 2]), c3 = __ldg(&g_cols[e + 3]);
        float w0 = __ldg(&g_wts[e]),     w1 = __ldg(&g_wts[e + 1]);
        float w2 = __ldg(&g_wts[e + 2]), w3 = __ldg(&g_wts[e + 3]);
        float4 v0 = s4[(size_t)c0 * 64 + fo];
        float4 v1 = s4[(size_t)c1 * 64 + fo];
        float4 v2 = s4[(size_t)c2 * 64 + fo];
        float4 v3 = s4[(size_t)c3 * 64 + fo];
        a.x += w0 * v0.x + w1 * v1.x + w2 * v2.x + w3 * v3.x;
        a.y += w0 * v0.y + w1 * v1.y + w2 * v2.y + w3 * v3.y;
        a.z += w0 * v0.z + w1 * v1.z + w2 * v2.z + w3 * v3.z;
        a.w += w0 * v0.w + w1 * v1.w + w2 * v2.w + w3 * v3.w;
    }
    for (; e < end; e++) {
        int c = __ldg(&g_cols[e]);
        float w = __ldg(&g_wts[e]);
        float4 v = s4[(size_t)c * 64 + fo];
        a.x += w * v.x; a.y += w * v.y; a.z += w * v.z; a.w += w * v.w;
    }
    uint2 hi, lo;
    split4((const float*)&a, hi, lo);
    *(uint2*)(dst + (size_t)row * 512 + fo * 4) = hi;
    *(uint2*)(dst + (size_t)row * 512 + 256 + fo * 4) = lo;
}

// ---------------- fused final GEMM (N=40) + log_softmax ----------------
__global__ void __launch_bounds__(256) gemm40_lsm_kernel(
    const float* __restrict__ A, const float* __restrict__ B,
    const float* __restrict__ bias, float* __restrict__ out, int M) {
    __shared__ float As[16][132];
    __shared__ float Bs[16][64];
    __shared__ float ls[128][44];
    int tid = threadIdx.x;
    int tn = tid % 16, tm = tid / 16;
    int m0 = blockIdx.x * 128;
    float acc[8][4];
#pragma unroll
    for (int i = 0; i < 8; i++)
#pragma unroll
        for (int j = 0; j < 4; j++) acc[i][j] = 0.f;

    for (int k0 = 0; k0 < NF; k0 += 16) {
        for (int i = tid; i < 128 * 16; i += 256) {
            int r = i >> 4, c = i & 15;
            int gm = m0 + r;
            As[c][r] = (gm < M) ? A[(size_t)gm * NF + k0 + c] : 0.f;
        }
        for (int i = tid; i < 16 * 64; i += 256) {
            int r = i >> 6, c = i & 63;
            Bs[r][c] = (c < 40) ? B[(size_t)(k0 + r) * 40 + c] : 0.f;
        }
        __syncthreads();
#pragma unroll
        for (int k = 0; k < 16; k++) {
            float av[8], bv[4];
#pragma unroll
            for (int i = 0; i < 8; i++) av[i] = As[k][tm * 8 + i];
#pragma unroll
            for (int j = 0; j < 4; j++) bv[j] = Bs[k][tn * 4 + j];
#pragma unroll
            for (int i = 0; i < 8; i++)
#pragma unroll
                for (int j = 0; j < 4; j++) acc[i][j] += av[i] * bv[j];
        }
        __syncthreads();
    }
#pragma unroll
    for (int i = 0; i < 8; i++)
#pragma unroll
        for (int j = 0; j < 4; j++) {
            int c = tn * 4 + j;
            if (c < 40) ls[tm * 8 + i][c] = acc[i][j] + bias[c];
        }
    __syncthreads();
    int wid = tid >> 5, lane = tid & 31;
    for (int i = 0; i < 16; i++) {
        int r = wid * 16 + i;
        int gr = m0 + r;
        if (gr >= M) continue;
        float v0 = ls[r][lane];
        float v1 = (lane < 8) ? ls[r][32 + lane] : -INFINITY;
        float m = fmaxf(v0, v1);
#pragma unroll
        for (int off = 16; off; off >>= 1) m = fmaxf(m, __shfl_xor_sync(0xffffffffu, m, off));
        float s = __expf(v0 - m) + ((lane < 8) ? __expf(v1 - m) : 0.f);
#pragma unroll
        for (int off = 16; off; off >>= 1) s += __shfl_xor_sync(0xffffffffu, s, off);
        float lse = m + __logf(s);
        out[(size_t)gr * 40 + lane] = v0 - lse;
        if (lane < 8) out[(size_t)gr * 40 + 32 + lane] = v1 - lse;
    }
}

// ---------------- launch ----------------
extern "C" void kernel_launch(void* const* d_in, const int* in_sizes, int n_in,
                              void* d_out, int out_size) {
    const float* x    = (const float*)d_in[0];
    const int*   erow = (const int*)d_in[1];
    const int*   ecol = (const int*)d_in[2];
    const float* ew   = (const float*)d_in[3];
    const float* W1 = (const float*)d_in[4];
    const float* b1 = (const float*)d_in[5];
    const float* W2 = (const float*)d_in[6];
    const float* b2 = (const float*)d_in[7];
    const float* W3 = (const float*)d_in[8];
    const float* b3 = (const float*)d_in[9];
    const float* W4 = (const float*)d_in[10];
    const float* b4 = (const float*)d_in[11];
    float* out = (float*)d_out;

    int E = in_sizes[1];
    int n = in_sizes[0] / NF;

    float *bufA, *bufB;
    __half *wh, *asp;
    int* rowptr;
    cudaGetSymbolAddress((void**)&bufA, g_bufA);
    cudaGetSymbolAddress((void**)&bufB, g_bufB);
    cudaGetSymbolAddress((void**)&rowptr, g_rowptr);
    cudaGetSymbolAddress((void**)&wh, g_Wh);
    cudaGetSymbolAddress((void**)&asp, g_Asp);

    cudaFuncSetAttribute(gemm_f16x2_kernel<true>,
                         cudaFuncAttributeMaxDynamicSharedMemorySize, GEMM_SMEM);
    cudaFuncSetAttribute(gemm_f16x2_kernel<false>,
                         cudaFuncAttributeMaxDynamicSharedMemorySize, GEMM_SMEM);

    // CSR build
    cudaMemsetAsync(rowptr, 0, (size_t)(n + 1) * sizeof(int));
    hist_kernel<<<(E + 255) / 256, 256>>>(erow, E);
    scan_kernel<<<1, 1024>>>(n);
    scatter_kernel<<<(E + 255) / 256, 256>>>(erow, ecol, ew, E);

    int spmm_blocks = (n * 64 + 255) / 256;
    int gemm_grid = (n + 127) / 128;

    // h0 = x + spmm(x)          -> Asp (fp16 split)   [4th kernel: profiled]
    spmm_res_split_kernel<<<spmm_blocks, 256>>>(x, asp, n);

    // weight prep (transpose to [N][K] fp16)
    prep_w_f16<<<256, 256>>>(W1, wh + 0 * (size_t)NF * NF);
    prep_w_f16<<<256, 256>>>(W2, wh + 1 * (size_t)NF * NF);
    prep_w_f16<<<256, 256>>>(W3, wh + 2 * (size_t)NF * NF);

    // h1 = relu(h0 @ W1 + b1)   -> bufB as fp16 split [M,512]
    gemm_f16x2_kernel<true><<<gemm_grid, 512, GEMM_SMEM>>>(
        asp, wh + 0 * (size_t)NF * NF, b1, nullptr, (__half*)bufB, n);
    // h2 = relu(h1 @ W2 + b2)   -> bufA fp32 (feeds spmm2)
    gemm_f16x2_kernel<false><<<gemm_grid, 512, GEMM_SMEM>>>(
        (const __half*)bufB, wh + 1 * (size_t)NF * NF, b2, bufA, nullptr, n);
    // h3 = h2 + spmm(h2)        -> Asp (fp16 split)
    spmm_res_split_kernel<<<spmm_blocks, 256>>>(bufA, asp, n);
    // h4 = relu(h3 @ W3 + b3)   -> bufB fp32 (h1-split dead)
    gemm_f16x2_kernel<false><<<gemm_grid, 512, GEMM_SMEM>>>(
        asp, wh + 2 * (size_t)NF * NF, b3, bufB, nullptr, n);
    // logits + log_softmax      -> d_out
    gemm40_lsm_kernel<<<gemm_grid, 256>>>(bufB, W4, b4, out, n);
}

// round 7
// speedup vs baseline: 1.2587x; 1.0867x over previous
#include <cuda_runtime.h>
#include <cuda_fp16.h>
#include <math.h>
#include <stdint.h>

#define NNODES 100000
#define NEDGES 3200000
#define NF 256

// ---------------- scratch (device globals; no allocs allowed) ----------------
__device__ float g_bufA[(size_t)NNODES * NF];           // fp32 [M,256]
__device__ float g_bufB[(size_t)NNODES * NF];           // aliased as fp16 split [M,512]
__device__ __half g_Asp[(size_t)NNODES * 512];          // fp16 split [hi(256)|lo(256)]
__device__ __half g_xh[(size_t)NNODES * NF];            // fp16 [M,256] gather operand
__device__ int   g_rowptr[NNODES + 1];
__device__ int   g_cursor[NNODES];
__device__ int   g_cols[NEDGES];
__device__ float g_wts[NEDGES];
__device__ __half g_Wh[3][NF * NF];                     // fp16 weights, [N][K] K-major

// ---------------- helpers ----------------
__device__ __forceinline__ uint32_t smem_u32(const void* p) {
    uint32_t a;
    asm("{ .reg .u64 t; cvta.to.shared.u64 t, %1; cvt.u32.u64 %0, t; }" : "=r"(a) : "l"(p));
    return a;
}

#define LDSM_X4(r0, r1, r2, r3, addr) \
    asm volatile("ldmatrix.sync.aligned.m8n8.x4.shared.b16 {%0,%1,%2,%3}, [%4];" \
                 : "=r"(r0), "=r"(r1), "=r"(r2), "=r"(r3) : "r"(addr))

__device__ __forceinline__ void mma_f16(float* d, const uint32_t* a, const uint32_t* b) {
    asm volatile(
        "mma.sync.aligned.m16n8k16.row.col.f32.f16.f16.f32 "
        "{%0,%1,%2,%3}, {%4,%5,%6,%7}, {%8,%9}, {%0,%1,%2,%3};"
        : "+f"(d[0]), "+f"(d[1]), "+f"(d[2]), "+f"(d[3])
        : "r"(a[0]), "r"(a[1]), "r"(a[2]), "r"(a[3]), "r"(b[0]), "r"(b[1]));
}

#define CP_ASYNC16(dst, src) \
    asm volatile("cp.async.cg.shared.global [%0], [%1], 16;" :: "r"(dst), "l"(src))
#define CP_COMMIT() asm volatile("cp.async.commit_group;")
#define CP_WAIT1() asm volatile("cp.async.wait_group 1;")
#define CP_WAIT0() asm volatile("cp.async.wait_group 0;")

__device__ __forceinline__ void split4(const float* f, uint2& hi, uint2& lo) {
    __half h[4], l[4];
#pragma unroll
    for (int e = 0; e < 4; e++) {
        h[e] = __float2half_rn(f[e]);
        l[e] = __float2half_rn(f[e] - __half2float(h[e]));
    }
    hi = *(uint2*)h;
    lo = *(uint2*)l;
}

// ---------------- x -> fp16 copy ----------------
__global__ void conv_f16_kernel(const float* __restrict__ src,
                                __half* __restrict__ dst, int total4) {
    int i = blockIdx.x * blockDim.x + threadIdx.x;
    if (i >= total4) return;
    float4 v = ((const float4*)src)[i];
    __half h[4] = {__float2half_rn(v.x), __float2half_rn(v.y),
                   __float2half_rn(v.z), __float2half_rn(v.w)};
    *(uint2*)(dst + (size_t)i * 4) = *(uint2*)h;
}

// ---------------- weight prep: W[K][N] fp32 -> Wh[N][K] fp16 ----------------
__global__ void prep_w_f16(const float* __restrict__ W, __half* __restrict__ Bh) {
    int n = blockIdx.x;
    int k = threadIdx.x;
    Bh[(size_t)n * NF + k] = __float2half_rn(W[(size_t)k * NF + n]);
}

// ---------------- fp16x2 GEMM: BM=128, BN=128, BK=64, 3-stage, occ=2 ----------------
// A: fp16 [M,512] (hi|lo); B: fp16 [256,256] K-major. grid=(ceil(M/128), 2).
// OUT: 0 -> fp32 [M,256]; 1 -> fp16 split [M,512]; 2 -> fp16 [M,256]
#define PITCH 72
#define A_SZ (128 * PITCH * 2)
#define B_SZ (128 * PITCH * 2)
#define STAGE_SZ (A_SZ + B_SZ)
#define GEMM_SMEM (3 * STAGE_SZ)

template <int OUT>
__global__ void __launch_bounds__(256, 2) gemm_f16x2_kernel(
    const __half* __restrict__ Ah, const __half* __restrict__ Bh,
    const float* __restrict__ bias, float* __restrict__ C,
    __half* __restrict__ Cs, int M) {
    extern __shared__ char smem[];
    uint32_t sbase = smem_u32(smem);

    int tid = threadIdx.x, lane = tid & 31, wid = tid >> 5;
    int m0 = blockIdx.x * 128;
    int n0 = blockIdx.y * 128;
    int wm = (wid >> 1) * 32;
    int wn = (wid & 1) * 64;

    int arow = tid >> 1, aq = tid & 1;   // 2 thr/row, 32 halves (64B) each
    int gmA = m0 + arow; if (gmA >= M) gmA = M - 1;

    float acc[2][8][4];
#pragma unroll
    for (int i = 0; i < 2; i++)
#pragma unroll
        for (int j = 0; j < 8; j++)
#pragma unroll
            for (int q = 0; q < 4; q++) acc[i][j][q] = 0.f;

    auto issue = [&](int it, int stg) {
        int kc = it >> 1, p = it & 1;
        uint32_t sA = sbase + stg * STAGE_SZ;
        uint32_t sB = sA + A_SZ;
        const __half* asrc = Ah + (size_t)gmA * 512 + p * 256 + kc * 64 + aq * 32;
        uint32_t adst = sA + (uint32_t)(arow * PITCH + aq * 32) * 2;
#pragma unroll
        for (int j = 0; j < 4; j++) CP_ASYNC16(adst + j * 16, asrc + j * 8);
        const __half* bsrc = Bh + (size_t)(n0 + arow) * NF + kc * 64 + aq * 32;
        uint32_t bdst = sB + (uint32_t)(arow * PITCH + aq * 32) * 2;
#pragma unroll
        for (int j = 0; j < 4; j++) CP_ASYNC16(bdst + j * 16, bsrc + j * 8);
        CP_COMMIT();
    };

    auto compute = [&](int stg) {
        uint32_t sA = sbase + stg * STAGE_SZ;
        uint32_t sB = sA + A_SZ;
#pragma unroll
        for (int ks = 0; ks < 4; ks++) {
            uint32_t af[2][4];
#pragma unroll
            for (int mt = 0; mt < 2; mt++) {
                uint32_t addr = sA +
                    (uint32_t)((wm + mt * 16 + (lane & 15)) * PITCH + ks * 16 +
                               ((lane >> 4) << 3)) * 2;
                LDSM_X4(af[mt][0], af[mt][1], af[mt][2], af[mt][3], addr);
            }
            uint32_t bf[4][4];
#pragma unroll
            for (int p = 0; p < 4; p++) {
                uint32_t addr = sB +
                    (uint32_t)((wn + p * 16 + ((lane >> 4) << 3) + (lane & 7)) * PITCH +
                               ks * 16 + ((lane >> 3) & 1) * 8) * 2;
                LDSM_X4(bf[p][0], bf[p][1], bf[p][2], bf[p][3], addr);
            }
#pragma unroll
            for (int mt = 0; mt < 2; mt++)
#pragma unroll
                for (int nt = 0; nt < 8; nt++)
                    mma_f16(acc[mt][nt], af[mt], &bf[nt >> 1][(nt & 1) * 2]);
        }
    };

    issue(0, 0);
    issue(1, 1);
    for (int it = 0; it < 8; it++) {
        if (it < 7) CP_WAIT1(); else CP_WAIT0();
        __syncthreads();
        compute(it % 3);
        if (it + 2 < 8) issue(it + 2, (it + 2) % 3);
    }

    // epilogue: bias + relu
#pragma unroll
    for (int mt = 0; mt < 2; mt++) {
        int rr[2];
        rr[0] = m0 + wm + mt * 16 + (lane >> 2);
        rr[1] = rr[0] + 8;
#pragma unroll
        for (int nt = 0; nt < 8; nt++) {
            int n = n0 + wn + nt * 8 + (lane & 3) * 2;
            float b0 = __ldg(bias + n), b1 = __ldg(bias + n + 1);
#pragma unroll
            for (int h = 0; h < 2; h++) {
                int r = rr[h];
                if (r >= M) continue;
                float v0 = fmaxf(acc[mt][nt][h * 2 + 0] + b0, 0.f);
                float v1 = fmaxf(acc[mt][nt][h * 2 + 1] + b1, 0.f);
                if (OUT == 1) {
                    __half h0 = __float2half_rn(v0), h1 = __float2half_rn(v1);
                    __half l0 = __float2half_rn(v0 - __half2float(h0));
                    __half l1 = __float2half_rn(v1 - __half2float(h1));
                    __half ph[2] = {h0, h1}, pl[2] = {l0, l1};
                    *(uint32_t*)(Cs + (size_t)r * 512 + n) = *(uint32_t*)ph;
                    *(uint32_t*)(Cs + (size_t)r * 512 + 256 + n) = *(uint32_t*)pl;
                } else if (OUT == 2) {
                    __half ph[2] = {__float2half_rn(v0), __float2half_rn(v1)};
                    *(uint32_t*)(Cs + (size_t)r * NF + n) = *(uint32_t*)ph;
                } else {
                    float2 o; o.x = v0; o.y = v1;
                    *(float2*)(C + (size_t)r * NF + n) = o;
                }
            }
        }
    }
}

// ---------------- CSR build ----------------
__global__ void hist_kernel(const int* __restrict__ erow, int E) {
    int i = blockIdx.x * blockDim.x + threadIdx.x;
    if (i < E) atomicAdd(&g_rowptr[erow[i]], 1);
}

__global__ void scan_kernel(int n) {
    __shared__ int part[1024];
    int t = threadIdx.x;
    int CH = (n + 1023) / 1024;
    int beg = t * CH;
    int end = min(beg + CH, n);
    int s = 0;
    for (int i = beg; i < end; i++) s += g_rowptr[i];
    part[t] = s;
    __syncthreads();
    for (int off = 1; off < 1024; off <<= 1) {
        int v = (t >= off) ? part[t - off] : 0;
        __syncthreads();
        part[t] += v;
        __syncthreads();
    }
    int base = (t == 0) ? 0 : part[t - 1];
    int run = base;
    for (int i = beg; i < end; i++) {
        int c = g_rowptr[i];
        g_rowptr[i] = run;
        g_cursor[i] = run;
        run += c;
    }
    if (t == 1023) g_rowptr[n] = part[1023];
}

__global__ void scatter_kernel(const int* __restrict__ erow,
                               const int* __restrict__ ecol,
                               const float* __restrict__ ew, int E) {
    int i = blockIdx.x * blockDim.x + threadIdx.x;
    if (i < E) {
        int r = erow[i];
        int pos = atomicAdd(&g_cursor[r], 1);
        g_cols[pos] = ecol[i];
        g_wts[pos] = ew[i];
    }
}

// ---------------- SPMM (fp16 gather) + residual -> fp16 split ----------------
// dst_split[row] = split( src[row] + sum_e w * src[col] ), src fp16 [n,256]
__global__ void spmm_f16_kernel(const __half* __restrict__ src,
                                __half* __restrict__ dst, int n) {
    int gw = (blockIdx.x * blockDim.x + threadIdx.x) >> 5;
    int row = gw >> 1;
    if (row >= n) return;
    int half_ = gw & 1;
    int lane = threadIdx.x & 31;
    int f4 = half_ * 32 + lane;           // uint2 index (4 halves) within 64/row
    const uint2* s2 = (const uint2*)src;  // row stride 64 uint2
    uint2 rv = s2[(size_t)row * 64 + f4];
    float2 p0 = __half22float2(*(__half2*)&rv.x);
    float2 p1 = __half22float2(*(__half2*)&rv.y);
    float ax = p0.x, ay = p0.y, az = p1.x, aw = p1.y;
    int beg = g_rowptr[row], end = g_rowptr[row + 1];
    int e = beg;
    for (; e + 4 <= end; e += 4) {
        int c0 = __ldg(&g_cols[e]),     c1 = __ldg(&g_cols[e + 1]);
        int c2 = __ldg(&g_cols[e + 2]), c3 = __ldg(&g_cols[e + 3]);
        float w0 = __ldg(&g_wts[e]),     w1 = __ldg(&g_wts[e + 1]);
        float w2 = __ldg(&g_wts[e + 2]), w3 = __ldg(&g_wts[e + 3]);
        uint2 v0 = s2[(size_t)c0 * 64 + f4];
        uint2 v1 = s2[(size_t)c1 * 64 + f4];
        uint2 v2 = s2[(size_t)c2 * 64 + f4];
        uint2 v3 = s2[(size_t)c3 * 64 + f4];
        float2 a0 = __half22float2(*(__half2*)&v0.x), b0 = __half22float2(*(__half2*)&v0.y);
        float2 a1 = __half22float2(*(__half2*)&v1.x), b1 = __half22float2(*(__half2*)&v1.y);
        float2 a2 = __half22float2(*(__half2*)&v2.x), b2 = __half22float2(*(__half2*)&v2.y);
        float2 a3 = __half22float2(*(__half2*)&v3.x), b3 = __half22float2(*(__half2*)&v3.y);
        ax += w0 * a0.x + w1 * a1.x + w2 * a2.x + w3 * a3.x;
        ay += w0 * a0.y + w1 * a1.y + w2 * a2.y + w3 * a3.y;
        az += w0 * b0.x + w1 * b1.x + w2 * b2.x + w3 * b3.x;
        aw += w0 * b0.y + w1 * b1.y + w2 * b2.y + w3 * b3.y;
    }
    for (; e < end; e++) {
        int c = __ldg(&g_cols[e]);
        float w = __ldg(&g_wts[e]);
        uint2 v = s2[(size_t)c * 64 + f4];
        float2 a = __half22float2(*(__half2*)&v.x), b = __half22float2(*(__half2*)&v.y);
        ax += w * a.x; ay += w * a.y; az += w * b.x; aw += w * b.y;
    }
    float res[4] = {ax, ay, az, aw};
    uint2 hi, lo;
    split4(res, hi, lo);
    *(uint2*)(dst + (size_t)row * 512 + f4 * 4) = hi;
    *(uint2*)(dst + (size_t)row * 512 + 256 + f4 * 4) = lo;
}

// ---------------- fused final GEMM (N=40) + log_softmax ----------------
__global__ void __launch_bounds__(256) gemm40_lsm_kernel(
    const float* __restrict__ A, const float* __restrict__ B,
    const float* __restrict__ bias, float* __restrict__ out, int M) {
    __shared__ float As[16][132];
    __shared__ float Bs[16][64];
    __shared__ float ls[128][44];
    int tid = threadIdx.x;
    int tn = tid % 16, tm = tid / 16;
    int m0 = blockIdx.x * 128;
    float acc[8][4];
#pragma unroll
    for (int i = 0; i < 8; i++)
#pragma unroll
        for (int j = 0; j < 4; j++) acc[i][j] = 0.f;

    for (int k0 = 0; k0 < NF; k0 += 16) {
        for (int i = tid; i < 128 * 16; i += 256) {
            int r = i >> 4, c = i & 15;
            int gm = m0 + r;
            As[c][r] = (gm < M) ? A[(size_t)gm * NF + k0 + c] : 0.f;
        }
        for (int i = tid; i < 16 * 64; i += 256) {
            int r = i >> 6, c = i & 63;
            Bs[r][c] = (c < 40) ? B[(size_t)(k0 + r) * 40 + c] : 0.f;
        }
        __syncthreads();
#pragma unroll
        for (int k = 0; k < 16; k++) {
            float av[8], bv[4];
#pragma unroll
            for (int i = 0; i < 8; i++) av[i] = As[k][tm * 8 + i];
#pragma unroll
            for (int j = 0; j < 4; j++) bv[j] = Bs[k][tn * 4 + j];
#pragma unroll
            for (int i = 0; i < 8; i++)
#pragma unroll
                for (int j = 0; j < 4; j++) acc[i][j] += av[i] * bv[j];
        }
        __syncthreads();
    }
#pragma unroll
    for (int i = 0; i < 8; i++)
#pragma unroll
        for (int j = 0; j < 4; j++) {
            int c = tn * 4 + j;
            if (c < 40) ls[tm * 8 + i][c] = acc[i][j] + bias[c];
        }
    __syncthreads();
    int wid = tid >> 5, lane = tid & 31;
    for (int i = 0; i < 16; i++) {
        int r = wid * 16 + i;
        int gr = m0 + r;
        if (gr >= M) continue;
        float v0 = ls[r][lane];
        float v1 = (lane < 8) ? ls[r][32 + lane] : -INFINITY;
        float m = fmaxf(v0, v1);
#pragma unroll
        for (int off = 16; off; off >>= 1) m = fmaxf(m, __shfl_xor_sync(0xffffffffu, m, off));
        float s = __expf(v0 - m) + ((lane < 8) ? __expf(v1 - m) : 0.f);
#pragma unroll
        for (int off = 16; off; off >>= 1) s += __shfl_xor_sync(0xffffffffu, s, off);
        float lse = m + __logf(s);
        out[(size_t)gr * 40 + lane] = v0 - lse;
        if (lane < 8) out[(size_t)gr * 40 + 32 + lane] = v1 - lse;
    }
}

// ---------------- launch ----------------
extern "C" void kernel_launch(void* const* d_in, const int* in_sizes, int n_in,
                              void* d_out, int out_size) {
    const float* x    = (const float*)d_in[0];
    const int*   erow = (const int*)d_in[1];
    const int*   ecol = (const int*)d_in[2];
    const float* ew   = (const float*)d_in[3];
    const float* W1 = (const float*)d_in[4];
    const float* b1 = (const float*)d_in[5];
    const float* W2 = (const float*)d_in[6];
    const float* b2 = (const float*)d_in[7];
    const float* W3 = (const float*)d_in[8];
    const float* b3 = (const float*)d_in[9];
    const float* W4 = (const float*)d_in[10];
    const float* b4 = (const float*)d_in[11];
    float* out = (float*)d_out;

    int E = in_sizes[1];
    int n = in_sizes[0] / NF;

    float *bufA, *bufB;
    __half *wh, *asp, *xh;
    int* rowptr;
    cudaGetSymbolAddress((void**)&bufA, g_bufA);
    cudaGetSymbolAddress((void**)&bufB, g_bufB);
    cudaGetSymbolAddress((void**)&rowptr, g_rowptr);
    cudaGetSymbolAddress((void**)&wh, g_Wh);
    cudaGetSymbolAddress((void**)&asp, g_Asp);
    cudaGetSymbolAddress((void**)&xh, g_xh);

    cudaFuncSetAttribute(gemm_f16x2_kernel<0>,
                         cudaFuncAttributeMaxDynamicSharedMemorySize, GEMM_SMEM);
    cudaFuncSetAttribute(gemm_f16x2_kernel<1>,
                         cudaFuncAttributeMaxDynamicSharedMemorySize, GEMM_SMEM);
    cudaFuncSetAttribute(gemm_f16x2_kernel<2>,
                         cudaFuncAttributeMaxDynamicSharedMemorySize, GEMM_SMEM);

    // x -> fp16
    conv_f16_kernel<<<(n * 64 + 255) / 256, 256>>>(x, xh, n * 64);

    // CSR build
    cudaMemsetAsync(rowptr, 0, (size_t)(n + 1) * sizeof(int));
    hist_kernel<<<(E + 255) / 256, 256>>>(erow, E);
    scan_kernel<<<1, 1024>>>(n);
    scatter_kernel<<<(E + 255) / 256, 256>>>(erow, ecol, ew, E);

    int spmm_blocks = (n * 64 + 255) / 256;
    dim3 gemm_grid((n + 127) / 128, 2);

    // h0 = x + spmm(x)           -> Asp (fp16 split)
    spmm_f16_kernel<<<spmm_blocks, 256>>>(xh, asp, n);

    // weight prep
    prep_w_f16<<<256, 256>>>(W1, wh + 0 * (size_t)NF * NF);
    prep_w_f16<<<256, 256>>>(W2, wh + 1 * (size_t)NF * NF);
    prep_w_f16<<<256, 256>>>(W3, wh + 2 * (size_t)NF * NF);

    // h1 = relu(h0 @ W1 + b1)    -> bufB as fp16 split [M,512]
    gemm_f16x2_kernel<1><<<gemm_grid, 256, GEMM_SMEM>>>(
        asp, wh + 0 * (size_t)NF * NF, b1, nullptr, (__half*)bufB, n);
    // h2 = relu(h1 @ W2 + b2)    -> xh (fp16 [M,256], xh dead after spmm1)
    gemm_f16x2_kernel<2><<<gemm_grid, 256, GEMM_SMEM>>>(
        (const __half*)bufB, wh + 1 * (size_t)NF * NF, b2, nullptr, xh, n);
    // h3 = h2 + spmm(h2)         -> Asp (fp16 split)
    spmm_f16_kernel<<<spmm_blocks, 256>>>(xh, asp, n);
    // h4 = relu(h3 @ W3 + b3)    -> bufA fp32
    gemm_f16x2_kernel<0><<<gemm_grid, 256, GEMM_SMEM>>>(
        asp, wh + 2 * (size_t)NF * NF, b3, bufA, nullptr, n);
    // logits + log_softmax       -> d_out
    gemm40_lsm_kernel<<<(n + 127) / 128, 256>>>(bufA, W4, b4, out, n);
}